// round 17
// baseline (speedup 1.0000x reference)
#include <cuda_runtime.h>
#include <cstdint>

// Problem constants (fixed by the reference setup)
#define BB   64
#define TT   1024
#define INC  16
#define NN   512
#define RR   16
#define OUTC 8
#define AA   0.1f   // DT / TAU

typedef unsigned long long u64;

// ---------------- packed f32x2 helpers (sm_103a dual-fp32 pipe) --------------
__device__ __forceinline__ u64 pk2(float lo, float hi) {
    u64 r; asm("mov.b64 %0, {%1, %2};" : "=l"(r) : "f"(lo), "f"(hi)); return r;
}
__device__ __forceinline__ void upk2(u64 v, float& lo, float& hi) {
    asm("mov.b64 {%0, %1}, %2;" : "=f"(lo), "=f"(hi) : "l"(v));
}
__device__ __forceinline__ u64 fma2(u64 a, u64 b, u64 c) {
    u64 d; asm("fma.rn.f32x2 %0, %1, %2, %3;" : "=l"(d) : "l"(a), "l"(b), "l"(c)); return d;
}
__device__ __forceinline__ u64 mul2(u64 a, u64 b) {
    u64 d; asm("mul.rn.f32x2 %0, %1, %2;" : "=l"(d) : "l"(a), "l"(b)); return d;
}
__device__ __forceinline__ u64 add2(u64 a, u64 b) {
    u64 d; asm("add.rn.f32x2 %0, %1, %2;" : "=l"(d) : "l"(a), "l"(b)); return d;
}

// Accurate-enough fast tanh: 1 - 2/(exp(2x)+1) via ex2.approx + rcp.approx.
__device__ __forceinline__ float fast_tanh(float x) {
    float e;
    asm("ex2.approx.f32 %0, %1;" : "=f"(e) : "f"(x * 2.885390082f)); // 2*log2(e)
    float r;
    asm("rcp.approx.f32 %0, %1;" : "=f"(r) : "f"(e + 1.0f));
    return fmaf(-2.0f, r, 1.0f);
}

// ---------------------------------------------------------------------------
// Kernel A: Inp[b,t,n] = sum_i X[b,t,i] * In_w[n,i], written into the hidden
// region of d_out (scratch aliasing with the scan). Tiled, In_w in registers.
// ---------------------------------------------------------------------------
#define IROWS 64
__global__ __launch_bounds__(256) void inp_kernel(const float* __restrict__ x,
                                                  const float* __restrict__ inw,
                                                  float* __restrict__ inp_out) {
    const int tid = threadIdx.x;
    const int r0  = blockIdx.x * IROWS;
    __shared__ float4 sx4[IROWS * INC / 4];

    sx4[tid] = reinterpret_cast<const float4*>(x)[(size_t)r0 * (INC / 4) + tid];

    const int n0 = tid * 2;
    float w0[INC], w1[INC];
    {
        const float4* a4 = reinterpret_cast<const float4*>(inw + (size_t)n0 * INC);
        const float4* b4 = reinterpret_cast<const float4*>(inw + (size_t)(n0 + 1) * INC);
#pragma unroll
        for (int i = 0; i < 4; i++) {
            float4 a = __ldg(&a4[i]);
            w0[4 * i + 0] = a.x; w0[4 * i + 1] = a.y; w0[4 * i + 2] = a.z; w0[4 * i + 3] = a.w;
            float4 c = __ldg(&b4[i]);
            w1[4 * i + 0] = c.x; w1[4 * i + 1] = c.y; w1[4 * i + 2] = c.z; w1[4 * i + 3] = c.w;
        }
    }
    __syncthreads();

    float2* out2 = reinterpret_cast<float2*>(inp_out) + (size_t)r0 * (NN / 2) + tid;

#pragma unroll 4
    for (int j = 0; j < IROWS; j++) {
        float acc0 = 0.0f, acc1 = 0.0f;
#pragma unroll
        for (int q = 0; q < 4; q++) {
            float4 xv = sx4[j * 4 + q];
            acc0 = fmaf(w0[4 * q + 0], xv.x, acc0);
            acc0 = fmaf(w0[4 * q + 1], xv.y, acc0);
            acc0 = fmaf(w0[4 * q + 2], xv.z, acc0);
            acc0 = fmaf(w0[4 * q + 3], xv.w, acc0);
            acc1 = fmaf(w1[4 * q + 0], xv.x, acc1);
            acc1 = fmaf(w1[4 * q + 1], xv.y, acc1);
            acc1 = fmaf(w1[4 * q + 2], xv.z, acc1);
            acc1 = fmaf(w1[4 * q + 3], xv.w, acc1);
        }
        out2[(size_t)j * (NN / 2)] = make_float2(acc0, acc1);
    }
}

// ---------------------------------------------------------------------------
// Kernel B (v9): sequential scan, TWO batches per thread (ILP interleaving).
// 32 CTAs x 128 threads; thread owns n0..n0+3 of batch 2*blk (chain A) AND
// batch 2*blk+1 (chain B). V/U register arrays are shared between chains.
// The two ~1000-cycle dependency chains interleave inside each thread, and
// both share the single implicit __syncthreads (BAR floor ~7cyc; the named
// barriers that sank the R10 TLP attempt cost ~47cyc).
// Profile evidence (R15): scan is pure exposed chain latency — occ 6.2%,
// DRAM 2.8%, fma 8.1%, issue 23% — so a second in-thread chain should fill
// the ~77% idle issue slots.
// hid[b,t,:] holds Inp on entry (consumed, overwritten with h_t).
// ---------------------------------------------------------------------------
__global__ __launch_bounds__(128, 1) void scan_kernel(const float* __restrict__ Vw,
                                                      const float* __restrict__ Uw,
                                                      const float* __restrict__ h0,
                                                      float* hid) {
    const int tid  = threadIdx.x;
    const int lane = tid & 31;
    const int warp = tid >> 5;          // 0..3
    const int n0   = tid * 4;
    const int bA   = blockIdx.x * 2;

    __shared__ u64 s_wsum[2][2][4][4][8];  // [buf][chain][warp][sublane c][pair a]

    // V packed over r-pairs: Vp[k][j] = (Vw[2j][n0+k], Vw[2j+1][n0+k])  (shared)
    u64 Vp[4][8];
#pragma unroll
    for (int j = 0; j < 8; j++)
#pragma unroll
        for (int k = 0; k < 4; k++)
            Vp[k][j] = pk2(Vw[(2 * j) * NN + n0 + k], Vw[(2 * j + 1) * NN + n0 + k]);

    // U rows contiguous in r: Up[k][j] = (Uw[n0+k][2j], Uw[n0+k][2j+1])  (shared)
    u64 Up[4][8];
#pragma unroll
    for (int k = 0; k < 4; k++) {
        const u64* up = reinterpret_cast<const u64*>(Uw + (size_t)(n0 + k) * RR);
#pragma unroll
        for (int j = 0; j < 8; j++) Up[k][j] = up[j];
    }

    float hA[4], hB[4];
#pragma unroll
    for (int k = 0; k < 4; k++) { hA[k] = h0[n0 + k]; hB[k] = hA[k]; }

    const size_t STRD = NN / 4;
    float4* hpA = reinterpret_cast<float4*>(hid) + (size_t)bA * TT * STRD + tid;
    float4* hpB = hpA + (size_t)TT * STRD;

    // 2-deep inp prefetch per chain (alias-safe)
    float4 ivA_a = __ldg(&hpA[0]);
    float4 ivA_b = __ldg(&hpA[STRD]);
    float4 ivB_a = __ldg(&hpB[0]);
    float4 ivB_b = __ldg(&hpB[STRD]);

    const unsigned FULL = 0xFFFFFFFFu;
    const int a_mine = lane & 7;        // pair this lane combines (redundant >=8)
    const int c_mine = lane & 3;        // sublane id
    const int a_st   = (lane >> 2) & 7; // pair this lane's fold survivor holds

    for (int s = 0; s < TT; s++) {
        const int sp = (s + 2 < TT) ? (s + 2) : (TT - 1);
        float4 ivA_c = __ldg(&hpA[(size_t)sp * STRD]);
        float4 ivB_c = __ldg(&hpB[(size_t)sp * STRD]);

        // tanh for both chains (8 independent MUFU pairs)
        float pA0 = fast_tanh(hA[0]), pA1 = fast_tanh(hA[1]);
        float pA2 = fast_tanh(hA[2]), pA3 = fast_tanh(hA[3]);
        float pB0 = fast_tanh(hB[0]), pB1 = fast_tanh(hB[1]);
        float pB2 = fast_tanh(hB[2]), pB3 = fast_tanh(hB[3]);

        u64 PHA0 = pk2(pA0, pA0), PHA1 = pk2(pA1, pA1);
        u64 PHA2 = pk2(pA2, pA2), PHA3 = pk2(pA3, pA3);
        u64 PHB0 = pk2(pB0, pB0), PHB1 = pk2(pB1, pB1);
        u64 PHB2 = pk2(pB2, pB2), PHB3 = pk2(pB3, pB3);

        // partials for both chains
        u64 PA[8], PB[8];
#pragma unroll
        for (int j = 0; j < 8; j++) {
            u64 eA = fma2(PHA1, Vp[1][j], mul2(PHA0, Vp[0][j]));
            u64 oA = fma2(PHA3, Vp[3][j], mul2(PHA2, Vp[2][j]));
            PA[j] = add2(eA, oA);
            u64 eB = fma2(PHB1, Vp[1][j], mul2(PHB0, Vp[0][j]));
            u64 oB = fma2(PHB3, Vp[3][j], mul2(PHB2, Vp[2][j]));
            PB[j] = add2(eB, oB);
        }

        // 3 sel-fold levels (bits 16, 8, 4), A and B interleaved
#pragma unroll
        for (int j = 0; j < 4; j++) {
            bool hi = (lane & 16) != 0;
            u64 kA = hi ? PA[j + 4] : PA[j];
            u64 sA = hi ? PA[j] : PA[j + 4];
            PA[j] = add2(kA, __shfl_xor_sync(FULL, sA, 16));
            u64 kB = hi ? PB[j + 4] : PB[j];
            u64 sB = hi ? PB[j] : PB[j + 4];
            PB[j] = add2(kB, __shfl_xor_sync(FULL, sB, 16));
        }
#pragma unroll
        for (int j = 0; j < 2; j++) {
            bool hi = (lane & 8) != 0;
            u64 kA = hi ? PA[j + 2] : PA[j];
            u64 sA = hi ? PA[j] : PA[j + 2];
            PA[j] = add2(kA, __shfl_xor_sync(FULL, sA, 8));
            u64 kB = hi ? PB[j + 2] : PB[j];
            u64 sB = hi ? PB[j] : PB[j + 2];
            PB[j] = add2(kB, __shfl_xor_sync(FULL, sB, 8));
        }
        {
            bool hi = (lane & 4) != 0;
            u64 kA = hi ? PA[1] : PA[0];
            u64 sA = hi ? PA[0] : PA[1];
            PA[0] = add2(kA, __shfl_xor_sync(FULL, sA, 4));
            u64 kB = hi ? PB[1] : PB[0];
            u64 sB = hi ? PB[0] : PB[1];
            PB[0] = add2(kB, __shfl_xor_sync(FULL, sB, 4));
        }

        // stores — distinct slots, unguarded; ONE implicit barrier for both
        const int buf = s & 1;
        s_wsum[buf][0][warp][c_mine][a_st] = PA[0];
        s_wsum[buf][1][warp][c_mine][a_st] = PB[0];
        __syncthreads();

        // redundant cross-warp combines (16 LDS.64 each, balanced trees)
        u64 combA, combB;
        {
            u64 x0 = add2(add2(s_wsum[buf][0][0][0][a_mine], s_wsum[buf][0][0][1][a_mine]),
                          add2(s_wsum[buf][0][0][2][a_mine], s_wsum[buf][0][0][3][a_mine]));
            u64 x1 = add2(add2(s_wsum[buf][0][1][0][a_mine], s_wsum[buf][0][1][1][a_mine]),
                          add2(s_wsum[buf][0][1][2][a_mine], s_wsum[buf][0][1][3][a_mine]));
            u64 x2 = add2(add2(s_wsum[buf][0][2][0][a_mine], s_wsum[buf][0][2][1][a_mine]),
                          add2(s_wsum[buf][0][2][2][a_mine], s_wsum[buf][0][2][3][a_mine]));
            u64 x3 = add2(add2(s_wsum[buf][0][3][0][a_mine], s_wsum[buf][0][3][1][a_mine]),
                          add2(s_wsum[buf][0][3][2][a_mine], s_wsum[buf][0][3][3][a_mine]));
            combA = add2(add2(x0, x1), add2(x2, x3));
        }
        {
            u64 x0 = add2(add2(s_wsum[buf][1][0][0][a_mine], s_wsum[buf][1][0][1][a_mine]),
                          add2(s_wsum[buf][1][0][2][a_mine], s_wsum[buf][1][0][3][a_mine]));
            u64 x1 = add2(add2(s_wsum[buf][1][1][0][a_mine], s_wsum[buf][1][1][1][a_mine]),
                          add2(s_wsum[buf][1][1][2][a_mine], s_wsum[buf][1][1][3][a_mine]));
            u64 x2 = add2(add2(s_wsum[buf][1][2][0][a_mine], s_wsum[buf][1][2][1][a_mine]),
                          add2(s_wsum[buf][1][2][2][a_mine], s_wsum[buf][1][2][3][a_mine]));
            u64 x3 = add2(add2(s_wsum[buf][1][3][0][a_mine], s_wsum[buf][1][3][1][a_mine]),
                          add2(s_wsum[buf][1][3][2][a_mine], s_wsum[buf][1][3][3][a_mine]));
            combB = add2(add2(x0, x1), add2(x2, x3));
        }

        // fused broadcast + rec accumulation (no LOW[] arrays): per pair a,
        // SHFL from lane a feeds 4 fma2 per chain directly.
        u64 accA[4], accB[4];
        {
            u64 lwA = __shfl_sync(FULL, combA, 0);
            u64 lwB = __shfl_sync(FULL, combB, 0);
#pragma unroll
            for (int k = 0; k < 4; k++) {
                accA[k] = mul2(lwA, Up[k][0]);
                accB[k] = mul2(lwB, Up[k][0]);
            }
        }
#pragma unroll
        for (int a = 1; a < 8; a++) {
            u64 lwA = __shfl_sync(FULL, combA, a);
            u64 lwB = __shfl_sync(FULL, combB, a);
#pragma unroll
            for (int k = 0; k < 4; k++) {
                accA[k] = fma2(lwA, Up[k][a], accA[k]);
                accB[k] = fma2(lwB, Up[k][a], accB[k]);
            }
        }

        float ivA[4] = {ivA_a.x, ivA_a.y, ivA_a.z, ivA_a.w};
        float ivB[4] = {ivB_a.x, ivB_a.y, ivB_a.z, ivB_a.w};
#pragma unroll
        for (int k = 0; k < 4; k++) {
            float lo, hi2;
            upk2(accA[k], lo, hi2);
            hA[k] = fmaf(1.0f - AA, hA[k], AA * ((lo + hi2) + ivA[k]));
            upk2(accB[k], lo, hi2);
            hB[k] = fmaf(1.0f - AA, hB[k], AA * ((lo + hi2) + ivB[k]));
        }

        hpA[(size_t)s * STRD] = make_float4(hA[0], hA[1], hA[2], hA[3]);
        hpB[(size_t)s * STRD] = make_float4(hB[0], hB[1], hB[2], hB[3]);

        ivA_a = ivA_b; ivA_b = ivA_c;
        ivB_a = ivB_b; ivB_b = ivB_c;
    }
}

// ---------------------------------------------------------------------------
// Kernel C: out[b,t,o] = sum_n tanh(hidden[b,t,n]) * Out_w[o,n]
// warp per (b,t) row; Out_w staged in smem; coalesced float4 hidden reads.
// ---------------------------------------------------------------------------
__global__ __launch_bounds__(256) void out_kernel(const float* __restrict__ hid,
                                                  const float* __restrict__ Ow,
                                                  float* __restrict__ outp) {
    __shared__ float4 s_w[OUTC * NN / 4];  // 16 KB
    const int tid  = threadIdx.x;
    const int lane = tid & 31;
    const int warp = tid >> 5;

    const float4* ow4 = reinterpret_cast<const float4*>(Ow);
    for (int i = tid; i < OUTC * NN / 4; i += 256) s_w[i] = ow4[i];
    __syncthreads();

    const size_t row = (size_t)blockIdx.x * 8 + warp;  // < B*T
    const float4* h4 = reinterpret_cast<const float4*>(hid) + row * (NN / 4);

    float acc[OUTC];
#pragma unroll
    for (int o = 0; o < OUTC; o++) acc[o] = 0.0f;

#pragma unroll
    for (int i = 0; i < 4; i++) {
        float4 hv = __ldg(&h4[i * 32 + lane]);
        float t0 = fast_tanh(hv.x);
        float t1 = fast_tanh(hv.y);
        float t2 = fast_tanh(hv.z);
        float t3 = fast_tanh(hv.w);
#pragma unroll
        for (int o = 0; o < OUTC; o++) {
            float4 wv = s_w[o * (NN / 4) + i * 32 + lane];
            acc[o] = fmaf(t0, wv.x, fmaf(t1, wv.y, fmaf(t2, wv.z, fmaf(t3, wv.w, acc[o]))));
        }
    }

    const unsigned FULL = 0xFFFFFFFFu;
#pragma unroll
    for (int j = 0; j < 4; j++) {
        bool hi = (lane & 16) != 0;
        float keep = hi ? acc[j + 4] : acc[j];
        float send = hi ? acc[j] : acc[j + 4];
        acc[j] = keep + __shfl_xor_sync(FULL, send, 16);
    }
#pragma unroll
    for (int j = 0; j < 2; j++) {
        bool hi = (lane & 8) != 0;
        float keep = hi ? acc[j + 2] : acc[j];
        float send = hi ? acc[j] : acc[j + 2];
        acc[j] = keep + __shfl_xor_sync(FULL, send, 8);
    }
    {
        bool hi = (lane & 4) != 0;
        float keep = hi ? acc[1] : acc[0];
        float send = hi ? acc[0] : acc[1];
        acc[0] = keep + __shfl_xor_sync(FULL, send, 4);
    }
    acc[0] += __shfl_xor_sync(FULL, acc[0], 2);
    acc[0] += __shfl_xor_sync(FULL, acc[0], 1);

    if ((lane & 3) == 0)
        outp[row * OUTC + ((lane >> 2) & 7)] = acc[0];
}

// ---------------------------------------------------------------------------
// kernel_launch: inputs per metadata order:
//   0 Batch_Input [B,T,INC], 1 In_w [N,INC], 2 V_w [R,N], 3 U_w [N,R],
//   4 Out_w [OUTC,N], 5 hidden_0 [N]
// d_out: hidden_t [B,T,N] followed by out [B,T,OUTC]  (float32)
// ---------------------------------------------------------------------------
extern "C" void kernel_launch(void* const* d_in, const int* in_sizes, int n_in,
                              void* d_out, int out_size) {
    const float* x   = (const float*)d_in[0];
    const float* inw = (const float*)d_in[1];
    const float* vw  = (const float*)d_in[2];
    const float* uw  = (const float*)d_in[3];
    const float* ow  = (const float*)d_in[4];
    const float* h0  = (const float*)d_in[5];

    float* hid  = (float*)d_out;
    float* outp = hid + (size_t)BB * TT * NN;

    inp_kernel<<<BB * TT / IROWS, 256>>>(x, inw, hid);  // Inp staged into hid
    scan_kernel<<<BB / 2, 128>>>(vw, uw, h0, hid);      // 2 batches per thread
    out_kernel<<<BB * TT / 8, 256>>>(hid, ow, outp);
}